// round 3
// baseline (speedup 1.0000x reference)
#include <cuda_runtime.h>
#include <cstdint>

#define NN 200000
#define DD 64
#define RR 32
#define BB 16
#define EE 3200000
#define TT 100000
#define KTOT (BB * DD + DD)   // 1088
#define SSTR 1092             // smem A row stride (words): bank = 4*row + k, conflict-free
typedef unsigned long long ull;

// ---------------- device scratch (static: allocation-free, ~180 MB) ----------------
__device__ float2   g_hp0[(size_t)NN * 32];   // embed, interleaved (l, l+32)
__device__ float2   g_h1[(size_t)NN * 32];    // layer-0 out, interleaved
__device__ float2   g_h2[(size_t)NN * 32];    // layer-1 out, interleaved
__device__ float2   g_wrelp[RR * 32];         // w_rel, interleaved
__device__ int      g_indeg[NN];
__device__ int      g_off[NN + 1];
__device__ int      g_cursor[NN];
__device__ int2     g_edge[EE];               // (src, etype) sorted by dst
__device__ uint32_t g_Wc0[KTOT * DD];         // [V0_flat ; wl0] pre-converted to tf32
__device__ uint32_t g_Wc1[KTOT * DD];

__device__ __forceinline__ uint32_t f2tf32(float f) {
    uint32_t r;
    asm("cvt.rna.tf32.f32 %0, %1;" : "=r"(r) : "f"(f));
    return r;
}
__device__ __forceinline__ ull pk2(float lo, float hi) {
    ull r; asm("mov.b64 %0, {%1, %2};" : "=l"(r) : "f"(lo), "f"(hi)); return r;
}
__device__ __forceinline__ void upk2(ull v, float& lo, float& hi) {
    asm("mov.b64 {%0, %1}, %2;" : "=f"(lo), "=f"(hi) : "l"(v));
}
__device__ __forceinline__ ull fma2(ull a, ull b, ull c) {
    ull d; asm("fma.rn.f32x2 %0, %1, %2, %3;" : "=l"(d) : "l"(a), "l"(b), "l"(c)); return d;
}

// ---------------- prep kernels ----------------
__global__ void zero_indeg_kernel(int n) {
    int i = blockIdx.x * blockDim.x + threadIdx.x;
    if (i < n) g_indeg[i] = 0;
}

__global__ void pack_h_kernel(const float* __restrict__ embed, int n) {
    int i = blockIdx.x * blockDim.x + threadIdx.x;
    if (i >= n * 32) return;
    int node = i >> 5, l = i & 31;
    g_hp0[i] = make_float2(embed[(size_t)node * DD + l], embed[(size_t)node * DD + 32 + l]);
}

__global__ void pack_wrel_kernel(const float* __restrict__ wrel) {
    int i = blockIdx.x * blockDim.x + threadIdx.x;
    if (i >= RR * 32) return;
    int r = i >> 5, l = i & 31;
    g_wrelp[i] = make_float2(wrel[r * DD + l], wrel[r * DD + 32 + l]);
}

__global__ void build_wc_kernel(const float* __restrict__ v0, const float* __restrict__ wl0,
                                const float* __restrict__ v1, const float* __restrict__ wl1) {
    int i = blockIdx.x * blockDim.x + threadIdx.x;
    if (i >= KTOT * DD) return;
    float a, b;
    if (i < BB * DD * DD) { a = v0[i]; b = v1[i]; }
    else                  { a = wl0[i - BB * DD * DD]; b = wl1[i - BB * DD * DD]; }
    g_Wc0[i] = f2tf32(a);
    g_Wc1[i] = f2tf32(b);
}

__global__ void hist_kernel(const int* __restrict__ dst, int e_cnt) {
    for (int e = blockIdx.x * blockDim.x + threadIdx.x; e < e_cnt; e += gridDim.x * blockDim.x)
        atomicAdd(&g_indeg[dst[e]], 1);
}

// single-block exclusive scan over indeg -> off, cursor
__global__ void scan_kernel(int n) {
    __shared__ int warpsum[32];
    __shared__ int s_carry;
    int t = threadIdx.x, lane = t & 31, w = t >> 5;
    if (t == 0) s_carry = 0;
    __syncthreads();
    for (int base = 0; base < n; base += 1024) {
        int i = base + t;
        int v = (i < n) ? g_indeg[i] : 0;
        int x = v;
        #pragma unroll
        for (int d = 1; d < 32; d <<= 1) {
            int y = __shfl_up_sync(0xffffffffu, x, d);
            if (lane >= d) x += y;
        }
        if (lane == 31) warpsum[w] = x;
        __syncthreads();
        if (w == 0) {
            int s = warpsum[lane];
            #pragma unroll
            for (int d = 1; d < 32; d <<= 1) {
                int y = __shfl_up_sync(0xffffffffu, s, d);
                if (lane >= d) s += y;
            }
            warpsum[lane] = s;
        }
        __syncthreads();
        int excl = s_carry + x - v + (w ? warpsum[w - 1] : 0);
        if (i < n) { g_off[i] = excl; g_cursor[i] = excl; }
        int tot = warpsum[31];
        __syncthreads();
        if (t == 0) s_carry += tot;
        __syncthreads();
    }
    if (t == 0) g_off[n] = s_carry;
}

__global__ void scatter_kernel(const int* __restrict__ src, const int* __restrict__ dst,
                               const int* __restrict__ et, int e_cnt) {
    for (int e = blockIdx.x * blockDim.x + threadIdx.x; e < e_cnt; e += gridDim.x * blockDim.x) {
        int p = atomicAdd(&g_cursor[dst[e]], 1);
        g_edge[p] = make_int2(src[e], et[e]);
    }
}

// ---------------- fused layer: c-space aggregation -> smem tf32 tile -> mma GEMM ---------
// block = 32 dst nodes, 512 threads (16 warps). Aggregation: warp handles 2 nodes,
// acc held packed f32x2 in registers. GEMM: 8 warps, warp tile m16n16, K=1088.
__global__ void __launch_bounds__(512, 1)
fused_layer_kernel(const float* __restrict__ cmat, const float* __restrict__ bias,
                   int layer, int n_nodes) {
    extern __shared__ uint32_t sA[];          // [32][SSTR] tf32
    __shared__ ull sc2[RR * 8];               // packed (c[r][j], c[r][j+8])

    const float2* __restrict__ hin = (layer == 0) ? g_hp0 : g_h1;
    int t = threadIdx.x, w = t >> 5, lane = t & 31;

    for (int i = t; i < RR * 8; i += 512) {
        int r = i >> 3, j = i & 7;
        sc2[i] = pk2(cmat[r * BB + j], cmat[r * BB + j + 8]);
    }
    __syncthreads();

    // ---- aggregation phase ----
    #pragma unroll
    for (int rep = 0; rep < 2; rep++) {
        int local = w * 2 + rep;
        int n = blockIdx.x * 32 + local;
        if (n < n_nodes) {
            ull accp[8], accq[8];
            #pragma unroll
            for (int j = 0; j < 8; j++) { accp[j] = 0ULL; accq[j] = 0ULL; }
            int beg = g_off[n], end = g_off[n + 1];
            int i = beg;
            for (; i + 1 < end; i += 2) {
                int2 e0 = g_edge[i];
                int2 e1 = g_edge[i + 1];
                float2 h0 = hin[(size_t)e0.x * 32 + lane];
                float2 h1 = hin[(size_t)e1.x * 32 + lane];
                ull xp0 = pk2(h0.x, h0.x), xq0 = pk2(h0.y, h0.y);
                ull xp1 = pk2(h1.x, h1.x), xq1 = pk2(h1.y, h1.y);
                const ull* c0 = &sc2[e0.y * 8];
                const ull* c1 = &sc2[e1.y * 8];
                #pragma unroll
                for (int j = 0; j < 8; j++) {
                    ull cj0 = c0[j], cj1 = c1[j];
                    accp[j] = fma2(cj0, xp0, accp[j]);
                    accq[j] = fma2(cj0, xq0, accq[j]);
                    accp[j] = fma2(cj1, xp1, accp[j]);
                    accq[j] = fma2(cj1, xq1, accq[j]);
                }
            }
            if (i < end) {
                int2 e0 = g_edge[i];
                float2 h0 = hin[(size_t)e0.x * 32 + lane];
                ull xp0 = pk2(h0.x, h0.x), xq0 = pk2(h0.y, h0.y);
                const ull* c0 = &sc2[e0.y * 8];
                #pragma unroll
                for (int j = 0; j < 8; j++) {
                    accp[j] = fma2(c0[j], xp0, accp[j]);
                    accq[j] = fma2(c0[j], xq0, accq[j]);
                }
            }
            // deposit tf32 A-tile row: k = b*64 + d  (d = lane / lane+32), then self-loop h
            uint32_t* row = &sA[(size_t)local * SSTR];
            #pragma unroll
            for (int j = 0; j < 8; j++) {
                float lo, hi;
                upk2(accp[j], lo, hi);
                row[j * 64 + lane]        = f2tf32(lo);   // b=j,   d=lane
                row[(j + 8) * 64 + lane]  = f2tf32(hi);   // b=j+8, d=lane
                upk2(accq[j], lo, hi);
                row[j * 64 + 32 + lane]       = f2tf32(lo);
                row[(j + 8) * 64 + 32 + lane] = f2tf32(hi);
            }
            float2 hs = hin[(size_t)n * 32 + lane];
            row[1024 + lane]      = f2tf32(hs.x);
            row[1024 + 32 + lane] = f2tf32(hs.y);
        }
    }
    __syncthreads();

    // ---- GEMM phase: (32 x 1088) @ (1088 x 64), 8 warps, warp tile m16n16 ----
    if (w < 8) {
        const uint32_t* __restrict__ Wc = (layer == 0) ? g_Wc0 : g_Wc1;
        float* __restrict__ hout = (float*)((layer == 0) ? g_h1 : g_h2);
        int wr = w & 1, wc = w >> 1;            // wc in 0..3, cols wc*16
        float c[2][4];
        #pragma unroll
        for (int a = 0; a < 2; a++)
            #pragma unroll
            for (int b = 0; b < 4; b++) c[a][b] = 0.f;

        int arow = wr * 16 + (lane >> 2);
        int ak = lane & 3;
        for (int k8 = 0; k8 < KTOT; k8 += 8) {
            uint32_t a0 = sA[(size_t)arow * SSTR + k8 + ak];
            uint32_t a1 = sA[(size_t)(arow + 8) * SSTR + k8 + ak];
            uint32_t a2 = sA[(size_t)arow * SSTR + k8 + ak + 4];
            uint32_t a3 = sA[(size_t)(arow + 8) * SSTR + k8 + ak + 4];
            #pragma unroll
            for (int nt = 0; nt < 2; nt++) {
                int ncol = wc * 16 + nt * 8 + (lane >> 2);
                uint32_t b0 = Wc[(k8 + ak) * DD + ncol];
                uint32_t b1 = Wc[(k8 + ak + 4) * DD + ncol];
                asm volatile(
                    "mma.sync.aligned.m16n8k8.row.col.f32.tf32.tf32.f32 "
                    "{%0,%1,%2,%3}, {%4,%5,%6,%7}, {%8,%9}, {%0,%1,%2,%3};\n"
                    : "+f"(c[nt][0]), "+f"(c[nt][1]), "+f"(c[nt][2]), "+f"(c[nt][3])
                    : "r"(a0), "r"(a1), "r"(a2), "r"(a3), "r"(b0), "r"(b1));
            }
        }
        const bool relu = (layer == 0);
        #pragma unroll
        for (int nt = 0; nt < 2; nt++) {
            int colb = wc * 16 + nt * 8 + 2 * (lane & 3);
            int row0 = blockIdx.x * 32 + wr * 16 + (lane >> 2);
            float bb0 = bias[colb], bb1 = bias[colb + 1];
            float v00 = c[nt][0] + bb0, v01 = c[nt][1] + bb1;
            float v10 = c[nt][2] + bb0, v11 = c[nt][3] + bb1;
            if (relu) {
                v00 = fmaxf(v00, 0.f); v01 = fmaxf(v01, 0.f);
                v10 = fmaxf(v10, 0.f); v11 = fmaxf(v11, 0.f);
            }
            // interleaved store: col c -> n*64 + 2*(c&31) + (c>>5)
            int p0 = 2 * (colb & 31) + (colb >> 5);
            int p1 = 2 * ((colb + 1) & 31) + ((colb + 1) >> 5);
            if (row0 < n_nodes) {
                hout[(size_t)row0 * 64 + p0] = v00;
                hout[(size_t)row0 * 64 + p1] = v01;
            }
            if (row0 + 8 < n_nodes) {
                hout[(size_t)(row0 + 8) * 64 + p0] = v10;
                hout[(size_t)(row0 + 8) * 64 + p1] = v11;
            }
        }
    }
}

// ---------------- DistMult scoring: warp per triplet (interleaved layouts) ----------------
__global__ void score_kernel(const int* __restrict__ head, const int* __restrict__ rel,
                             const int* __restrict__ tail, float* __restrict__ out, int t_cnt) {
    int w = (blockIdx.x * blockDim.x + threadIdx.x) >> 5;
    int lane = threadIdx.x & 31;
    if (w >= t_cnt) return;
    float2 a = g_h2[(size_t)head[w] * 32 + lane];
    float2 r = g_wrelp[rel[w] * 32 + lane];
    float2 b = g_h2[(size_t)tail[w] * 32 + lane];
    float p = a.x * r.x * b.x + a.y * r.y * b.y;
    #pragma unroll
    for (int d = 16; d > 0; d >>= 1) p += __shfl_xor_sync(0xffffffffu, p, d);
    if (lane == 0) out[w] = p;
}

// ---------------- launch ----------------
extern "C" void kernel_launch(void* const* d_in, const int* in_sizes, int n_in,
                              void* d_out, int out_size) {
    const int*   src   = (const int*)d_in[0];
    const int*   dst   = (const int*)d_in[1];
    const int*   ety   = (const int*)d_in[2];
    const int*   head  = (const int*)d_in[3];
    const int*   rel   = (const int*)d_in[4];
    const int*   tail  = (const int*)d_in[5];
    const float* embed = (const float*)d_in[6];
    const float* v0    = (const float*)d_in[7];
    const float* c0    = (const float*)d_in[8];
    const float* wl0   = (const float*)d_in[9];
    const float* b0    = (const float*)d_in[10];
    const float* v1    = (const float*)d_in[11];
    const float* c1    = (const float*)d_in[12];
    const float* wl1   = (const float*)d_in[13];
    const float* b1    = (const float*)d_in[14];
    const float* wrel  = (const float*)d_in[15];
    float* out = (float*)d_out;

    int E = in_sizes[0];
    int T = in_sizes[3];
    int N = in_sizes[6] / DD;
    if (N > NN) N = NN;
    if (E > EE) E = EE;
    if (T > TT) T = TT;

    const int smem_bytes = 32 * SSTR * 4;   // 139,776 B
    static int attr_done = 0;
    if (!attr_done) {
        cudaFuncSetAttribute(fused_layer_kernel,
                             cudaFuncAttributeMaxDynamicSharedMemorySize, smem_bytes);
        attr_done = 1;
    }

    // prep: CSR by dst + layout repacks + tf32 weight build
    zero_indeg_kernel<<<(N + 255) / 256, 256>>>(N);
    pack_h_kernel<<<(N * 32 + 255) / 256, 256>>>(embed, N);
    pack_wrel_kernel<<<(RR * 32 + 255) / 256, 256>>>(wrel);
    build_wc_kernel<<<(KTOT * DD + 255) / 256, 256>>>(v0, wl0, v1, wl1);
    hist_kernel<<<1024, 256>>>(dst, E);
    scan_kernel<<<1, 1024>>>(N);
    scatter_kernel<<<1024, 256>>>(src, dst, ety, E);

    // layer 0 (relu) and layer 1 (no activation), fused aggregate+GEMM
    fused_layer_kernel<<<(N + 31) / 32, 512, smem_bytes>>>(c0, b0, 0, N);
    fused_layer_kernel<<<(N + 31) / 32, 512, smem_bytes>>>(c1, b1, 1, N);

    // DistMult scoring
    score_kernel<<<(T + 7) / 8, 256>>>(head, rel, tail, out, T);
}

// round 4
// speedup vs baseline: 1.7548x; 1.7548x over previous
#include <cuda_runtime.h>
#include <cuda_fp16.h>
#include <cstdint>

#define NN 200000
#define DD 64
#define RR 32
#define BB 16
#define EE 3200000
#define TT 100000
#define KTOT (BB * DD + DD)   // 1088
typedef unsigned long long ull;

// GEMM tiling
#define BM 128
#define BK 64                 // halves per K-stage
#define NKSTAGES (KTOT / BK)  // 17
#define ARS 72                // smem A/B row stride in halves (144B): conflict-free
#define A_STG_BYTES (BM * ARS * 2)       // 18432
#define B_STG_BYTES (64 * ARS * 2)       // 9216
#define SMEM_GEMM (2 * A_STG_BYTES + 2 * B_STG_BYTES)  // 55296

// ---------------- device scratch (static: allocation-free) ----------------
__device__ __half  g_acc[(size_t)NN * KTOT];  // (N,1088) accumulator, fp16 (435 MB)
__device__ float2  g_hp0[(size_t)NN * 32];    // embed, interleaved (l, l+32)
__device__ float2  g_h1[(size_t)NN * 32];     // layer-0 out, interleaved
__device__ float2  g_h2[(size_t)NN * 32];     // layer-1 out, interleaved
__device__ float2  g_wrelp[RR * 32];          // w_rel, interleaved
__device__ int     g_indeg[NN];
__device__ int     g_off[NN + 1];
__device__ int     g_cursor[NN];
__device__ int2    g_edge[EE];                // (src, etype) sorted by dst
__device__ __half  g_WcT0[DD * KTOT];         // B transposed: [n][k], fp16
__device__ __half  g_WcT1[DD * KTOT];

__device__ __forceinline__ ull pk2(float lo, float hi) {
    ull r; asm("mov.b64 %0, {%1, %2};" : "=l"(r) : "f"(lo), "f"(hi)); return r;
}
__device__ __forceinline__ void upk2(ull v, float& lo, float& hi) {
    asm("mov.b64 {%0, %1}, %2;" : "=f"(lo), "=f"(hi) : "l"(v));
}
__device__ __forceinline__ ull fma2(ull a, ull b, ull c) {
    ull d; asm("fma.rn.f32x2 %0, %1, %2, %3;" : "=l"(d) : "l"(a), "l"(b), "l"(c)); return d;
}
#define CP_ASYNC16(dst32, src, sz) \
    asm volatile("cp.async.cg.shared.global [%0], [%1], 16, %2;" \
                 :: "r"(dst32), "l"(src), "r"(sz))

// ---------------- prep kernels ----------------
__global__ void zero_indeg_kernel(int n) {
    int i = blockIdx.x * blockDim.x + threadIdx.x;
    if (i < n) g_indeg[i] = 0;
}

__global__ void pack_h_kernel(const float* __restrict__ embed, int n) {
    int i = blockIdx.x * blockDim.x + threadIdx.x;
    if (i >= n * 32) return;
    int node = i >> 5, l = i & 31;
    g_hp0[i] = make_float2(embed[(size_t)node * DD + l], embed[(size_t)node * DD + 32 + l]);
}

__global__ void pack_wrel_kernel(const float* __restrict__ wrel) {
    int i = blockIdx.x * blockDim.x + threadIdx.x;
    if (i >= RR * 32) return;
    int r = i >> 5, l = i & 31;
    g_wrelp[i] = make_float2(wrel[r * DD + l], wrel[r * DD + 32 + l]);
}

// B^T build: WcT[n][k] = (k<1024) ? V[b=k>>6][d=k&63][n] : wl[k-1024][n], as fp16
__global__ void build_wct_kernel(const float* __restrict__ v0, const float* __restrict__ wl0,
                                 const float* __restrict__ v1, const float* __restrict__ wl1) {
    int i = blockIdx.x * blockDim.x + threadIdx.x;
    if (i >= DD * KTOT) return;
    int n = i / KTOT, k = i - n * KTOT;
    float a, b;
    if (k < BB * DD) {
        int bidx = k >> 6, d = k & 63;
        a = v0[bidx * DD * DD + d * DD + n];
        b = v1[bidx * DD * DD + d * DD + n];
    } else {
        int d = k - BB * DD;
        a = wl0[d * DD + n];
        b = wl1[d * DD + n];
    }
    g_WcT0[i] = __float2half_rn(a);
    g_WcT1[i] = __float2half_rn(b);
}

__global__ void hist_kernel(const int* __restrict__ dst, int e_cnt) {
    for (int e = blockIdx.x * blockDim.x + threadIdx.x; e < e_cnt; e += gridDim.x * blockDim.x)
        atomicAdd(&g_indeg[dst[e]], 1);
}

// single-block exclusive scan over indeg -> off, cursor
__global__ void scan_kernel(int n) {
    __shared__ int warpsum[32];
    __shared__ int s_carry;
    int t = threadIdx.x, lane = t & 31, w = t >> 5;
    if (t == 0) s_carry = 0;
    __syncthreads();
    for (int base = 0; base < n; base += 1024) {
        int i = base + t;
        int v = (i < n) ? g_indeg[i] : 0;
        int x = v;
        #pragma unroll
        for (int d = 1; d < 32; d <<= 1) {
            int y = __shfl_up_sync(0xffffffffu, x, d);
            if (lane >= d) x += y;
        }
        if (lane == 31) warpsum[w] = x;
        __syncthreads();
        if (w == 0) {
            int s = warpsum[lane];
            #pragma unroll
            for (int d = 1; d < 32; d <<= 1) {
                int y = __shfl_up_sync(0xffffffffu, s, d);
                if (lane >= d) s += y;
            }
            warpsum[lane] = s;
        }
        __syncthreads();
        int excl = s_carry + x - v + (w ? warpsum[w - 1] : 0);
        if (i < n) { g_off[i] = excl; g_cursor[i] = excl; }
        int tot = warpsum[31];
        __syncthreads();
        if (t == 0) s_carry += tot;
        __syncthreads();
    }
    if (t == 0) g_off[n] = s_carry;
}

__global__ void scatter_kernel(const int* __restrict__ src, const int* __restrict__ dst,
                               const int* __restrict__ et, int e_cnt) {
    for (int e = blockIdx.x * blockDim.x + threadIdx.x; e < e_cnt; e += gridDim.x * blockDim.x) {
        int p = atomicAdd(&g_cursor[dst[e]], 1);
        g_edge[p] = make_int2(src[e], et[e]);
    }
}

// ---------------- c-space aggregation: warp per dst node, fp16 output ----------------
__global__ void aggregate_kernel(const float* __restrict__ cmat, int layer, int n_nodes) {
    __shared__ ull sc2[RR * 8];               // packed (c[r][j], c[r][j+8])
    const float2* __restrict__ hin = (layer == 0) ? g_hp0 : g_h1;
    int t = threadIdx.x, lane = t & 31;
    for (int i = t; i < RR * 8; i += blockDim.x) {
        int r = i >> 3, j = i & 7;
        sc2[i] = pk2(cmat[r * BB + j], cmat[r * BB + j + 8]);
    }
    __syncthreads();
    int n = blockIdx.x * (blockDim.x >> 5) + (t >> 5);
    if (n >= n_nodes) return;

    ull accp[8], accq[8];
    #pragma unroll
    for (int j = 0; j < 8; j++) { accp[j] = 0ULL; accq[j] = 0ULL; }
    int beg = g_off[n], end = g_off[n + 1];
    int i = beg;
    for (; i + 1 < end; i += 2) {
        int2 e0 = g_edge[i];
        int2 e1 = g_edge[i + 1];
        float2 h0 = hin[(size_t)e0.x * 32 + lane];
        float2 h1 = hin[(size_t)e1.x * 32 + lane];
        ull xp0 = pk2(h0.x, h0.x), xq0 = pk2(h0.y, h0.y);
        ull xp1 = pk2(h1.x, h1.x), xq1 = pk2(h1.y, h1.y);
        const ull* c0 = &sc2[e0.y * 8];
        const ull* c1 = &sc2[e1.y * 8];
        #pragma unroll
        for (int j = 0; j < 8; j++) {
            ull cj0 = c0[j], cj1 = c1[j];
            accp[j] = fma2(cj0, xp0, accp[j]);
            accq[j] = fma2(cj0, xq0, accq[j]);
            accp[j] = fma2(cj1, xp1, accp[j]);
            accq[j] = fma2(cj1, xq1, accq[j]);
        }
    }
    if (i < end) {
        int2 e0 = g_edge[i];
        float2 h0 = hin[(size_t)e0.x * 32 + lane];
        ull xp0 = pk2(h0.x, h0.x), xq0 = pk2(h0.y, h0.y);
        const ull* c0 = &sc2[e0.y * 8];
        #pragma unroll
        for (int j = 0; j < 8; j++) {
            accp[j] = fma2(c0[j], xp0, accp[j]);
            accq[j] = fma2(c0[j], xq0, accq[j]);
        }
    }
    __half* row = &g_acc[(size_t)n * KTOT];
    #pragma unroll
    for (int j = 0; j < 8; j++) {
        float lo, hi;
        upk2(accp[j], lo, hi);
        row[j * 64 + lane]       = __float2half_rn(lo);   // b=j,   d=lane
        row[(j + 8) * 64 + lane] = __float2half_rn(hi);   // b=j+8, d=lane
        upk2(accq[j], lo, hi);
        row[j * 64 + 32 + lane]       = __float2half_rn(lo);
        row[(j + 8) * 64 + 32 + lane] = __float2half_rn(hi);
    }
    float2 hs = hin[(size_t)n * 32 + lane];
    row[1024 + lane] = __float2half_rn(hs.x);
    row[1056 + lane] = __float2half_rn(hs.y);
}

// ---------------- pipelined fp16 GEMM: (N,1088) @ (1088,64) + bias (+relu) --------------
// block 128 rows, 256 threads (8 warps, 4x2), warp tile m32n32, cp.async double buffer
__global__ void __launch_bounds__(256)
gemm_kernel(const float* __restrict__ bias, int layer, int nrows) {
    extern __shared__ char sm[];
    const __half* __restrict__ Ag = g_acc;
    const __half* __restrict__ Bt = (layer == 0) ? g_WcT0 : g_WcT1;
    float* __restrict__ outp = (float*)((layer == 0) ? g_h1 : g_h2);
    const bool relu = (layer == 0);

    int t = threadIdx.x, w = t >> 5, lane = t & 31;
    int g = lane >> 2, tig = lane & 3;
    int wr = w >> 1, wc = w & 1;
    int blockRow = blockIdx.x * BM;

    float c[2][4][4];
    #pragma unroll
    for (int m2 = 0; m2 < 2; m2++)
        #pragma unroll
        for (int nb = 0; nb < 4; nb++)
            #pragma unroll
            for (int q = 0; q < 4; q++) c[m2][nb][q] = 0.f;

    // stage loader: A 128x64 halves, B 64x64 halves, padded rows (ARS halves)
    auto load_stage = [&](int s, int ks) {
        char* As = sm + s * A_STG_BYTES;
        char* Bs = sm + 2 * A_STG_BYTES + s * B_STG_BYTES;
        #pragma unroll
        for (int r = 0; r < 4; r++) {                // A: 1024 chunks of 16B
            int cidx = t + r * 256;
            int row = cidx >> 3, seg = cidx & 7;
            int grow = blockRow + row;
            int sz = (grow < nrows) ? 16 : 0;
            int gr = (grow < nrows) ? grow : (nrows - 1);
            const __half* src = Ag + (size_t)gr * KTOT + ks * BK + seg * 8;
            uint32_t dst = (uint32_t)__cvta_generic_to_shared(As + row * (ARS * 2) + seg * 16);
            CP_ASYNC16(dst, src, sz);
        }
        #pragma unroll
        for (int r = 0; r < 2; r++) {                // B: 512 chunks of 16B
            int cidx = t + r * 256;
            int nrow = cidx >> 3, seg = cidx & 7;
            const __half* src = Bt + (size_t)nrow * KTOT + ks * BK + seg * 8;
            uint32_t dst = (uint32_t)__cvta_generic_to_shared(Bs + nrow * (ARS * 2) + seg * 16);
            CP_ASYNC16(dst, src, 16);
        }
    };

    load_stage(0, 0);
    asm volatile("cp.async.commit_group;");

    #pragma unroll 1
    for (int ks = 0; ks < NKSTAGES; ks++) {
        if (ks + 1 < NKSTAGES) load_stage((ks + 1) & 1, ks + 1);
        asm volatile("cp.async.commit_group;");      // uniform (possibly empty) group
        asm volatile("cp.async.wait_group 1;");
        __syncthreads();

        int s = ks & 1;
        const __half* As = (const __half*)(sm + s * A_STG_BYTES);
        const __half* Bs = (const __half*)(sm + 2 * A_STG_BYTES + s * B_STG_BYTES);
        #pragma unroll
        for (int k16 = 0; k16 < BK / 16; k16++) {
            int kb = k16 * 16;
            uint32_t a[2][4];
            #pragma unroll
            for (int m2 = 0; m2 < 2; m2++) {
                const __half* ab = As + (wr * 32 + m2 * 16 + g) * ARS + kb + 2 * tig;
                a[m2][0] = *(const uint32_t*)(ab);
                a[m2][1] = *(const uint32_t*)(ab + 8 * ARS);
                a[m2][2] = *(const uint32_t*)(ab + 8);
                a[m2][3] = *(const uint32_t*)(ab + 8 * ARS + 8);
            }
            #pragma unroll
            for (int nb = 0; nb < 4; nb++) {
                const __half* bb = Bs + (wc * 32 + nb * 8 + g) * ARS + kb + 2 * tig;
                uint32_t b0 = *(const uint32_t*)(bb);
                uint32_t b1 = *(const uint32_t*)(bb + 8);
                #pragma unroll
                for (int m2 = 0; m2 < 2; m2++) {
                    asm volatile(
                        "mma.sync.aligned.m16n8k16.row.col.f32.f16.f16.f32 "
                        "{%0,%1,%2,%3}, {%4,%5,%6,%7}, {%8,%9}, {%0,%1,%2,%3};\n"
                        : "+f"(c[m2][nb][0]), "+f"(c[m2][nb][1]),
                          "+f"(c[m2][nb][2]), "+f"(c[m2][nb][3])
                        : "r"(a[m2][0]), "r"(a[m2][1]), "r"(a[m2][2]), "r"(a[m2][3]),
                          "r"(b0), "r"(b1));
                }
            }
        }
        __syncthreads();
    }

    // epilogue: bias, relu, interleaved store  (col n -> flat 2*(n&31)+(n>>5))
    #pragma unroll
    for (int m2 = 0; m2 < 2; m2++) {
        #pragma unroll
        for (int nb = 0; nb < 4; nb++) {
            int colb = wc * 32 + nb * 8 + 2 * tig;
            int row0 = blockRow + wr * 32 + m2 * 16 + g;
            float bb0 = bias[colb], bb1 = bias[colb + 1];
            float v00 = c[m2][nb][0] + bb0, v01 = c[m2][nb][1] + bb1;
            float v10 = c[m2][nb][2] + bb0, v11 = c[m2][nb][3] + bb1;
            if (relu) {
                v00 = fmaxf(v00, 0.f); v01 = fmaxf(v01, 0.f);
                v10 = fmaxf(v10, 0.f); v11 = fmaxf(v11, 0.f);
            }
            int p0 = 2 * (colb & 31) + (colb >> 5);
            int p1 = 2 * ((colb + 1) & 31) + ((colb + 1) >> 5);
            if (row0 < nrows) {
                outp[(size_t)row0 * 64 + p0] = v00;
                outp[(size_t)row0 * 64 + p1] = v01;
            }
            if (row0 + 8 < nrows) {
                outp[(size_t)(row0 + 8) * 64 + p0] = v10;
                outp[(size_t)(row0 + 8) * 64 + p1] = v11;
            }
        }
    }
}

// ---------------- DistMult scoring: warp per triplet (interleaved layouts) ----------------
__global__ void score_kernel(const int* __restrict__ head, const int* __restrict__ rel,
                             const int* __restrict__ tail, float* __restrict__ out, int t_cnt) {
    int w = (blockIdx.x * blockDim.x + threadIdx.x) >> 5;
    int lane = threadIdx.x & 31;
    if (w >= t_cnt) return;
    float2 a = g_h2[(size_t)head[w] * 32 + lane];
    float2 r = g_wrelp[rel[w] * 32 + lane];
    float2 b = g_h2[(size_t)tail[w] * 32 + lane];
    float p = a.x * r.x * b.x + a.y * r.y * b.y;
    #pragma unroll
    for (int d = 16; d > 0; d >>= 1) p += __shfl_xor_sync(0xffffffffu, p, d);
    if (lane == 0) out[w] = p;
}

// ---------------- launch ----------------
extern "C" void kernel_launch(void* const* d_in, const int* in_sizes, int n_in,
                              void* d_out, int out_size) {
    const int*   src   = (const int*)d_in[0];
    const int*   dst   = (const int*)d_in[1];
    const int*   ety   = (const int*)d_in[2];
    const int*   head  = (const int*)d_in[3];
    const int*   rel   = (const int*)d_in[4];
    const int*   tail  = (const int*)d_in[5];
    const float* embed = (const float*)d_in[6];
    const float* v0    = (const float*)d_in[7];
    const float* c0    = (const float*)d_in[8];
    const float* wl0   = (const float*)d_in[9];
    const float* b0    = (const float*)d_in[10];
    const float* v1    = (const float*)d_in[11];
    const float* c1    = (const float*)d_in[12];
    const float* wl1   = (const float*)d_in[13];
    const float* b1    = (const float*)d_in[14];
    const float* wrel  = (const float*)d_in[15];
    float* out = (float*)d_out;

    int E = in_sizes[0];
    int T = in_sizes[3];
    int N = in_sizes[6] / DD;
    if (N > NN) N = NN;
    if (E > EE) E = EE;
    if (T > TT) T = TT;

    static int attr_done = 0;
    if (!attr_done) {
        cudaFuncSetAttribute(gemm_kernel,
                             cudaFuncAttributeMaxDynamicSharedMemorySize, SMEM_GEMM);
        attr_done = 1;
    }

    // prep: CSR by dst + layout repacks + fp16 B^T build
    zero_indeg_kernel<<<(N + 255) / 256, 256>>>(N);
    pack_h_kernel<<<(N * 32 + 255) / 256, 256>>>(embed, N);
    pack_wrel_kernel<<<(RR * 32 + 255) / 256, 256>>>(wrel);
    build_wct_kernel<<<(DD * KTOT + 255) / 256, 256>>>(v0, wl0, v1, wl1);
    hist_kernel<<<1024, 256>>>(dst, E);
    scan_kernel<<<1, 1024>>>(N);
    scatter_kernel<<<1024, 256>>>(src, dst, ety, E);

    // layer 0 (relu)
    aggregate_kernel<<<(N + 7) / 8, 256>>>(c0, 0, N);
    gemm_kernel<<<(N + BM - 1) / BM, 256, SMEM_GEMM>>>(b0, 0, N);

    // layer 1 (no activation)
    aggregate_kernel<<<(N + 7) / 8, 256>>>(c1, 1, N);
    gemm_kernel<<<(N + BM - 1) / BM, 256, SMEM_GEMM>>>(b1, 1, N);

    // DistMult scoring
    score_kernel<<<(T + 7) / 8, 256>>>(head, rel, tail, out, T);
}

// round 6
// speedup vs baseline: 2.1341x; 1.2161x over previous
#include <cuda_runtime.h>
#include <cuda_fp16.h>
#include <cstdint>

#define NN 200000
#define DD 64
#define RR 32
#define BB 16
#define EE 3200000
#define TT 100000
#define KTOT (BB * DD + BB * 0 + DD)   // 1088

// GEMM tiling
#define BM 128
#define BK 64                 // halves per K-stage
#define NKSTAGES (KTOT / BK)  // 17
#define ARS 72                // smem row stride in halves (144B): conflict-free
#define A_STG_BYTES (BM * ARS * 2)       // 18432
#define B_STG_BYTES (64 * ARS * 2)       // 9216
#define SMEM_GEMM (2 * A_STG_BYTES + 2 * B_STG_BYTES)  // 55296

// aggregation staging
#define AGG_WARPS 8
#define HSTR 72   // hstage row stride (halves): banks 4r mod 32, distinct for ldmatrix
#define CSTR 24   // c_chunk row stride (halves): banks 12r mod 32, distinct

// ---------------- device scratch (static: allocation-free) ----------------
__device__ __half  g_acc[(size_t)NN * KTOT];  // (N,1088) accumulator rows, fp16
__device__ __half  g_hp16[(size_t)NN * DD];   // embed fp16, natural layout
__device__ __half  g_h1[(size_t)NN * DD];     // layer-0 out fp16, natural
__device__ float   g_h2[(size_t)NN * DD];     // layer-1 out fp32, natural
__device__ int     g_indeg[NN];
__device__ int     g_off[NN + 1];
__device__ int     g_cursor[NN];
__device__ int2    g_edge[EE];                // (src, etype) sorted by dst
__device__ __half  g_WcT0[DD * KTOT];         // B transposed [n][k], fp16
__device__ __half  g_WcT1[DD * KTOT];

#define CP_ASYNC16(dst32, src, sz) \
    asm volatile("cp.async.cg.shared.global [%0], [%1], 16, %2;" \
                 :: "r"(dst32), "l"(src), "r"(sz))
#define LDSM_X4_T(r0, r1, r2, r3, addr) \
    asm volatile("ldmatrix.sync.aligned.m8n8.x4.trans.shared.b16 {%0,%1,%2,%3}, [%4];" \
                 : "=r"(r0), "=r"(r1), "=r"(r2), "=r"(r3) : "r"(addr))
#define MMA16816(c, a0, a1, a2, a3, b0, b1) \
    asm volatile("mma.sync.aligned.m16n8k16.row.col.f32.f16.f16.f32 " \
                 "{%0,%1,%2,%3}, {%4,%5,%6,%7}, {%8,%9}, {%0,%1,%2,%3};\n" \
                 : "+f"((c)[0]), "+f"((c)[1]), "+f"((c)[2]), "+f"((c)[3]) \
                 : "r"(a0), "r"(a1), "r"(a2), "r"(a3), "r"(b0), "r"(b1))

// ---------------- prep kernels ----------------
__global__ void zero_indeg_kernel(int n) {
    int i = blockIdx.x * blockDim.x + threadIdx.x;
    if (i < n) g_indeg[i] = 0;
}

__global__ void pack_h_kernel(const float* __restrict__ embed, int n) {
    int i = blockIdx.x * blockDim.x + threadIdx.x;
    if (i >= n * 32) return;
    float2 v = ((const float2*)embed)[i];
    ((__half2*)g_hp16)[i] = __floats2half2_rn(v.x, v.y);
}

// B^T build: WcT[n][k] = (k<1024) ? V[b=k>>6][d=k&63][n] : wl[k-1024][n]
__global__ void build_wct_kernel(const float* __restrict__ v0, const float* __restrict__ wl0,
                                 const float* __restrict__ v1, const float* __restrict__ wl1) {
    int i = blockIdx.x * blockDim.x + threadIdx.x;
    if (i >= DD * KTOT) return;
    int n = i / KTOT, k = i - n * KTOT;
    float a, b;
    if (k < BB * DD) {
        int bidx = k >> 6, d = k & 63;
        a = v0[bidx * DD * DD + d * DD + n];
        b = v1[bidx * DD * DD + d * DD + n];
    } else {
        int d = k - BB * DD;
        a = wl0[d * DD + n];
        b = wl1[d * DD + n];
    }
    g_WcT0[i] = __float2half_rn(a);
    g_WcT1[i] = __float2half_rn(b);
}

__global__ void hist_kernel(const int* __restrict__ dst, int e_cnt) {
    for (int e = blockIdx.x * blockDim.x + threadIdx.x; e < e_cnt; e += gridDim.x * blockDim.x)
        atomicAdd(&g_indeg[dst[e]], 1);
}

// single-block exclusive scan over indeg -> off, cursor
__global__ void scan_kernel(int n) {
    __shared__ int warpsum[32];
    __shared__ int s_carry;
    int t = threadIdx.x, lane = t & 31, w = t >> 5;
    if (t == 0) s_carry = 0;
    __syncthreads();
    for (int base = 0; base < n; base += 1024) {
        int i = base + t;
        int v = (i < n) ? g_indeg[i] : 0;
        int x = v;
        #pragma unroll
        for (int d = 1; d < 32; d <<= 1) {
            int y = __shfl_up_sync(0xffffffffu, x, d);
            if (lane >= d) x += y;
        }
        if (lane == 31) warpsum[w] = x;
        __syncthreads();
        if (w == 0) {
            int s = warpsum[lane];
            #pragma unroll
            for (int d = 1; d < 32; d <<= 1) {
                int y = __shfl_up_sync(0xffffffffu, s, d);
                if (lane >= d) s += y;
            }
            warpsum[lane] = s;
        }
        __syncthreads();
        int excl = s_carry + x - v + (w ? warpsum[w - 1] : 0);
        if (i < n) { g_off[i] = excl; g_cursor[i] = excl; }
        int tot = warpsum[31];
        __syncthreads();
        if (t == 0) s_carry += tot;
        __syncthreads();
    }
    if (t == 0) g_off[n] = s_carry;
}

__global__ void scatter_kernel(const int* __restrict__ src, const int* __restrict__ dst,
                               const int* __restrict__ et, int e_cnt) {
    for (int e = blockIdx.x * blockDim.x + threadIdx.x; e < e_cnt; e += gridDim.x * blockDim.x) {
        int p = atomicAdd(&g_cursor[dst[e]], 1);
        g_edge[p] = make_int2(src[e], et[e]);
    }
}

// ---------------- tensor-core aggregation: warp per dst node --------------------------
// Per 16-edge chunk: stage h rows (16x64 fp16) + c matrix (16x16 fp16) in warp-private
// smem, ldmatrix.x4.trans fragments, 8x mma.m16n8k16 -> acc[b=16][d=64] in fp32 frags.
__global__ void __launch_bounds__(256)
aggregate_kernel(const float* __restrict__ cmat, int layer, int n_nodes) {
    __shared__ __align__(16) __half c16[33 * 16];                 // row 32 = zeros (pad)
    __shared__ __align__(16) __half hstage[AGG_WARPS][16 * HSTR];
    __shared__ __align__(16) __half cst[AGG_WARPS][16 * CSTR];
    const __half* __restrict__ hin = (layer == 0) ? g_hp16 : g_h1;
    int t = threadIdx.x, w = t >> 5, lane = t & 31;

    for (int i = t; i < 32 * 16; i += 256) c16[i] = __float2half_rn(cmat[i]);
    for (int i = 32 * 16 + t; i < 33 * 16; i += 256) c16[i] = __ushort_as_half(0);
    __syncthreads();

    int n = blockIdx.x * AGG_WARPS + w;
    if (n >= n_nodes) return;

    float acc[8][4];
    #pragma unroll
    for (int i = 0; i < 8; i++)
        #pragma unroll
        for (int j = 0; j < 4; j++) acc[i][j] = 0.f;

    int beg = g_off[n], end = g_off[n + 1];
    int row = lane >> 1, part = lane & 1;
    int g = lane >> 2, tig = lane & 3;

    // ldmatrix source addresses (u32 shared-space)
    uint32_t hb = (uint32_t)__cvta_generic_to_shared(hstage[w]);
    uint32_t cb = (uint32_t)__cvta_generic_to_shared(cst[w]);
    // A tiles: (k0-7,m0-7)->a0, (k0-7,m8-15)->a1, (k8-15,m0-7)->a2, (k8-15,m8-15)->a3
    uint32_t aaddr = cb + (uint32_t)((((lane & 7) + ((lane & 16) >> 1)) * CSTR + (lane & 8)) * 2);
    // B tiles: (k0-7,n0-7)->b0, (k8-15,n0-7)->b1, then n+8 pair
    uint32_t baddr = hb + (uint32_t)(((lane & 15) * HSTR + ((lane & 16) >> 1)) * 2);

    for (int kc = beg; kc < end; kc += 16) {
        __syncwarp();                                   // WAR: prior ldsm done
        int ei = kc + row;
        int ec = (ei < end) ? ei : end - 1;
        int2 e = g_edge[ec];
        int rsel = (ei < end) ? e.y : 32;
        // stage h row (2 lanes per row, 64B each)
        const uint4* hsrc = (const uint4*)(hin + (size_t)e.x * DD + part * 32);
        uint4 v0 = hsrc[0], v1 = hsrc[1], v2 = hsrc[2], v3 = hsrc[3];
        uint4* hdst = (uint4*)(hstage[w] + row * HSTR + part * 32);
        hdst[0] = v0; hdst[1] = v1; hdst[2] = v2; hdst[3] = v3;
        // stage c row (16B per lane)
        *(uint4*)(cst[w] + row * CSTR + part * 8) = *(const uint4*)(c16 + rsel * 16 + part * 8);
        __syncwarp();                                   // RAW: stage visible

        uint32_t a0, a1, a2, a3;
        LDSM_X4_T(a0, a1, a2, a3, aaddr);
        #pragma unroll
        for (int dt = 0; dt < 4; dt++) {
            uint32_t b0, b1, b2, b3;
            LDSM_X4_T(b0, b1, b2, b3, baddr + dt * 32);
            MMA16816(acc[2 * dt],     a0, a1, a2, a3, b0, b1);
            MMA16816(acc[2 * dt + 1], a0, a1, a2, a3, b2, b3);
        }
    }

    // write acc rows: k = b*64 + d  (b = g, g+8; d = 8*dt + 2*tig)
    __half* arow = g_acc + (size_t)n * KTOT;
    #pragma unroll
    for (int dt = 0; dt < 8; dt++) {
        int d = dt * 8 + 2 * tig;
        *(__half2*)(arow + g * 64 + d)       = __floats2half2_rn(acc[dt][0], acc[dt][1]);
        *(__half2*)(arow + (g + 8) * 64 + d) = __floats2half2_rn(acc[dt][2], acc[dt][3]);
    }
    // self-loop: k = 1024 + d
    *(uint32_t*)(arow + 1024 + 2 * lane) = ((const uint32_t*)(hin + (size_t)n * DD))[lane];
}

// ---------------- pipelined fp16 GEMM: (N,1088) @ (1088,64) + bias (+relu) --------------
__global__ void __launch_bounds__(256)
gemm_kernel(const float* __restrict__ bias, int layer, int nrows) {
    extern __shared__ char sm[];
    const __half* __restrict__ Ag = g_acc;
    const __half* __restrict__ Bt = (layer == 0) ? g_WcT0 : g_WcT1;

    int t = threadIdx.x, w = t >> 5, lane = t & 31;
    int g = lane >> 2, tig = lane & 3;
    int wr = w >> 1, wc = w & 1;
    int blockRow = blockIdx.x * BM;

    float c[2][4][4];
    #pragma unroll
    for (int m2 = 0; m2 < 2; m2++)
        #pragma unroll
        for (int nb = 0; nb < 4; nb++)
            #pragma unroll
            for (int q = 0; q < 4; q++) c[m2][nb][q] = 0.f;

    auto load_stage = [&](int s, int ks) {
        char* As = sm + s * A_STG_BYTES;
        char* Bs = sm + 2 * A_STG_BYTES + s * B_STG_BYTES;
        #pragma unroll
        for (int r = 0; r < 4; r++) {
            int cidx = t + r * 256;
            int row = cidx >> 3, seg = cidx & 7;
            int grow = blockRow + row;
            int sz = (grow < nrows) ? 16 : 0;
            int gr = (grow < nrows) ? grow : (nrows - 1);
            const __half* src = Ag + (size_t)gr * KTOT + ks * BK + seg * 8;
            uint32_t dst = (uint32_t)__cvta_generic_to_shared(As + row * (ARS * 2) + seg * 16);
            CP_ASYNC16(dst, src, sz);
        }
        #pragma unroll
        for (int r = 0; r < 2; r++) {
            int cidx = t + r * 256;
            int nrow = cidx >> 3, seg = cidx & 7;
            const __half* src = Bt + (size_t)nrow * KTOT + ks * BK + seg * 8;
            uint32_t dst = (uint32_t)__cvta_generic_to_shared(Bs + nrow * (ARS * 2) + seg * 16);
            CP_ASYNC16(dst, src, 16);
        }
    };

    load_stage(0, 0);
    asm volatile("cp.async.commit_group;");

    #pragma unroll 1
    for (int ks = 0; ks < NKSTAGES; ks++) {
        if (ks + 1 < NKSTAGES) load_stage((ks + 1) & 1, ks + 1);
        asm volatile("cp.async.commit_group;");
        asm volatile("cp.async.wait_group 1;");
        __syncthreads();

        int s = ks & 1;
        const __half* As = (const __half*)(sm + s * A_STG_BYTES);
        const __half* Bs = (const __half*)(sm + 2 * A_STG_BYTES + s * B_STG_BYTES);
        #pragma unroll
        for (int k16 = 0; k16 < BK / 16; k16++) {
            int kb = k16 * 16;
            uint32_t a[2][4];
            #pragma unroll
            for (int m2 = 0; m2 < 2; m2++) {
                const __half* ab = As + (wr * 32 + m2 * 16 + g) * ARS + kb + 2 * tig;
                a[m2][0] = *(const uint32_t*)(ab);
                a[m2][1] = *(const uint32_t*)(ab + 8 * ARS);
                a[m2][2] = *(const uint32_t*)(ab + 8);
                a[m2][3] = *(const uint32_t*)(ab + 8 * ARS + 8);
            }
            #pragma unroll
            for (int nb = 0; nb < 4; nb++) {
                const __half* bb = Bs + (wc * 32 + nb * 8 + g) * ARS + kb + 2 * tig;
                uint32_t b0 = *(const uint32_t*)(bb);
                uint32_t b1 = *(const uint32_t*)(bb + 8);
                #pragma unroll
                for (int m2 = 0; m2 < 2; m2++)
                    MMA16816(c[m2][nb], a[m2][0], a[m2][1], a[m2][2], a[m2][3], b0, b1);
            }
        }
        __syncthreads();
    }

    // epilogue: bias (+relu); layer0 -> fp16 g_h1, layer1 -> fp32 g_h2 (natural layout)
    #pragma unroll
    for (int m2 = 0; m2 < 2; m2++) {
        #pragma unroll
        for (int nb = 0; nb < 4; nb++) {
            int colb = wc * 32 + nb * 8 + 2 * tig;
            int row0 = blockRow + wr * 32 + m2 * 16 + g;
            float bb0 = bias[colb], bb1 = bias[colb + 1];
            float v00 = c[m2][nb][0] + bb0, v01 = c[m2][nb][1] + bb1;
            float v10 = c[m2][nb][2] + bb0, v11 = c[m2][nb][3] + bb1;
            if (layer == 0) {
                v00 = fmaxf(v00, 0.f); v01 = fmaxf(v01, 0.f);
                v10 = fmaxf(v10, 0.f); v11 = fmaxf(v11, 0.f);
                if (row0 < nrows)
                    *(__half2*)(g_h1 + (size_t)row0 * DD + colb) = __floats2half2_rn(v00, v01);
                if (row0 + 8 < nrows)
                    *(__half2*)(g_h1 + (size_t)(row0 + 8) * DD + colb) = __floats2half2_rn(v10, v11);
            } else {
                if (row0 < nrows)
                    *(float2*)(g_h2 + (size_t)row0 * DD + colb) = make_float2(v00, v01);
                if (row0 + 8 < nrows)
                    *(float2*)(g_h2 + (size_t)(row0 + 8) * DD + colb) = make_float2(v10, v11);
            }
        }
    }
}

// ---------------- DistMult scoring: warp per triplet (natural layouts) ----------------
__global__ void score_kernel(const int* __restrict__ head, const int* __restrict__ rel,
                             const int* __restrict__ tail, const float* __restrict__ wrel,
                             float* __restrict__ out, int t_cnt) {
    int w = (blockIdx.x * blockDim.x + threadIdx.x) >> 5;
    int lane = threadIdx.x & 31;
    if (w >= t_cnt) return;
    float2 a = *(const float2*)(g_h2 + (size_t)head[w] * DD + 2 * lane);
    float2 r = *(const float2*)(wrel + (size_t)rel[w] * DD + 2 * lane);
    float2 b = *(const float2*)(g_h2 + (size_t)tail[w] * DD + 2 * lane);
    float p = a.x * r.x * b.x + a.y * r.y * b.y;
    #pragma unroll
    for (int d = 16; d > 0; d >>= 1) p += __shfl_xor_sync(0xffffffffu, p, d);
    if (lane == 0) out[w] = p;
}

// ---------------- launch ----------------
extern "C" void kernel_launch(void* const* d_in, const int* in_sizes, int n_in,
                              void* d_out, int out_size) {
    const int*   src   = (const int*)d_in[0];
    const int*   dst   = (const int*)d_in[1];
    const int*   ety   = (const int*)d_in[2];
    const int*   head  = (const int*)d_in[3];
    const int*   rel   = (const int*)d_in[4];
    const int*   tail  = (const int*)d_in[5];
    const float* embed = (const float*)d_in[6];
    const float* v0    = (const float*)d_in[7];
    const float* c0    = (const float*)d_in[8];
    const float* wl0   = (const float*)d_in[9];
    const float* b0    = (const float*)d_in[10];
    const float* v1    = (const float*)d_in[11];
    const float* c1    = (const float*)d_in[12];
    const float* wl1   = (const float*)d_in[13];
    const float* b1    = (const float*)d_in[14];
    const float* wrel  = (const float*)d_in[15];
    float* out = (float*)d_out;

    int E = in_sizes[0];
    int T = in_sizes[3];
    int N = in_sizes[6] / DD;
    if (N > NN) N = NN;
    if (E > EE) E = EE;
    if (T > TT) T = TT;

    cudaFuncSetAttribute(gemm_kernel,
                         cudaFuncAttributeMaxDynamicSharedMemorySize, SMEM_GEMM);

    // prep: CSR by dst + fp16 repacks + B^T build
    zero_indeg_kernel<<<(N + 255) / 256, 256>>>(N);
    pack_h_kernel<<<(N * 32 + 255) / 256, 256>>>(embed, N);
    build_wct_kernel<<<(DD * KTOT + 255) / 256, 256>>>(v0, wl0, v1, wl1);
    hist_kernel<<<1024, 256>>>(dst, E);
    scan_kernel<<<1, 1024>>>(N);
    scatter_kernel<<<1024, 256>>>(src, dst, ety, E);

    // layer 0 (relu)
    aggregate_kernel<<<(N + AGG_WARPS - 1) / AGG_WARPS, 256>>>(c0, 0, N);
    gemm_kernel<<<(N + BM - 1) / BM, 256, SMEM_GEMM>>>(b0, 0, N);

    // layer 1 (no activation)
    aggregate_kernel<<<(N + AGG_WARPS - 1) / AGG_WARPS, 256>>>(c1, 1, N);
    gemm_kernel<<<(N + BM - 1) / BM, 256, SMEM_GEMM>>>(b1, 1, N);

    // DistMult scoring
    score_kernel<<<(T + 7) / 8, 256>>>(head, rel, tail, wrel, out, T);
}

// round 8
// speedup vs baseline: 2.1346x; 1.0002x over previous
#include <cuda_runtime.h>
#include <cuda_fp16.h>
#include <cstdint>

#define NN 200000
#define DD 64
#define RR 32
#define BB 16
#define EE 3200000
#define TT 100000
#define KTOT (BB * DD + DD)   // 1088

// fused-layer tiling
#define NODES_BLK 64
#define THREADS 512           // 16 warps
#define NPW 4                 // nodes per warp (sequential)
#define ASTR 1096             // sA row stride in halves -> row bank base 4*row
#define BRS 72                // B stage row stride in halves
#define NBSTAGES (KTOT / 64)  // 17 B stages of 64 halves
// dynamic smem layout (bytes)
#define SA_BYTES   (NODES_BLK * ASTR * 2)      // 140288
#define B_STG_B    (64 * BRS * 2)              // 9216
#define OFF_B      SA_BYTES                    // two B stages
#define OFF_HST    (OFF_B + 2 * B_STG_B)       // 158720
#define HSTR 72
#define CSTR 24
#define OFF_CST    (OFF_HST + 16 * 16 * HSTR * 2)   // +36864 = 195584
#define SMEM_TOTAL (OFF_CST + 16 * 16 * CSTR * 2)   // +12288 = 207872

// ---------------- device scratch (static: allocation-free) ----------------
__device__ __half  g_hp16[(size_t)NN * DD];   // embed fp16, natural layout
__device__ __half  g_h1[(size_t)NN * DD];     // layer-0 out fp16, natural
__device__ float   g_h2[(size_t)NN * DD];     // layer-1 out fp32, natural
__device__ int     g_indeg[NN];
__device__ int     g_off[NN + 1];
__device__ int     g_cursor[NN];
__device__ int2    g_edge[EE];                // (src, etype) sorted by dst
__device__ __half  g_WcT0[DD * KTOT];         // B transposed [n][k], fp16
__device__ __half  g_WcT1[DD * KTOT];

#define CP_ASYNC16(dst32, src) \
    asm volatile("cp.async.cg.shared.global [%0], [%1], 16;" :: "r"(dst32), "l"(src))
#define LDSM_X4_T(r0, r1, r2, r3, addr) \
    asm volatile("ldmatrix.sync.aligned.m8n8.x4.trans.shared.b16 {%0,%1,%2,%3}, [%4];" \
                 : "=r"(r0), "=r"(r1), "=r"(r2), "=r"(r3) : "r"(addr))
#define MMA16816(c, a0, a1, a2, a3, b0, b1) \
    asm volatile("mma.sync.aligned.m16n8k16.row.col.f32.f16.f16.f32 " \
                 "{%0,%1,%2,%3}, {%4,%5,%6,%7}, {%8,%9}, {%0,%1,%2,%3};\n" \
                 : "+f"((c)[0]), "+f"((c)[1]), "+f"((c)[2]), "+f"((c)[3]) \
                 : "r"(a0), "r"(a1), "r"(a2), "r"(a3), "r"(b0), "r"(b1))

__device__ __forceinline__ int swz(int c) { return c ^ ((c >> 3) & 7); }

// ---------------- prep kernels ----------------
__global__ void zero_indeg_kernel(int n) {
    int i = blockIdx.x * blockDim.x + threadIdx.x;
    if (i < n) g_indeg[i] = 0;
}

__global__ void pack_h_kernel(const float* __restrict__ embed, int n) {
    int i = blockIdx.x * blockDim.x + threadIdx.x;
    if (i >= n * 32) return;
    float2 v = ((const float2*)embed)[i];
    ((__half2*)g_hp16)[i] = __floats2half2_rn(v.x, v.y);
}

// B^T build: WcT[n][k] = (k<1024) ? V[b=k>>6][d=k&63][n] : wl[k-1024][n]
__global__ void build_wct_kernel(const float* __restrict__ v0, const float* __restrict__ wl0,
                                 const float* __restrict__ v1, const float* __restrict__ wl1) {
    int i = blockIdx.x * blockDim.x + threadIdx.x;
    if (i >= DD * KTOT) return;
    int n = i / KTOT, k = i - n * KTOT;
    float a, b;
    if (k < BB * DD) {
        int bidx = k >> 6, d = k & 63;
        a = v0[bidx * DD * DD + d * DD + n];
        b = v1[bidx * DD * DD + d * DD + n];
    } else {
        int d = k - BB * DD;
        a = wl0[d * DD + n];
        b = wl1[d * DD + n];
    }
    g_WcT0[i] = __float2half_rn(a);
    g_WcT1[i] = __float2half_rn(b);
}

__global__ void hist_kernel(const int* __restrict__ dst, int e_cnt) {
    for (int e = blockIdx.x * blockDim.x + threadIdx.x; e < e_cnt; e += gridDim.x * blockDim.x)
        atomicAdd(&g_indeg[dst[e]], 1);
}

// single-block exclusive scan over indeg -> off, cursor
__global__ void scan_kernel(int n) {
    __shared__ int warpsum[32];
    __shared__ int s_carry;
    int t = threadIdx.x, lane = t & 31, w = t >> 5;
    if (t == 0) s_carry = 0;
    __syncthreads();
    for (int base = 0; base < n; base += 1024) {
        int i = base + t;
        int v = (i < n) ? g_indeg[i] : 0;
        int x = v;
        #pragma unroll
        for (int d = 1; d < 32; d <<= 1) {
            int y = __shfl_up_sync(0xffffffffu, x, d);
            if (lane >= d) x += y;
        }
        if (lane == 31) warpsum[w] = x;
        __syncthreads();
        if (w == 0) {
            int s = warpsum[lane];
            #pragma unroll
            for (int d = 1; d < 32; d <<= 1) {
                int y = __shfl_up_sync(0xffffffffu, s, d);
                if (lane >= d) s += y;
            }
            warpsum[lane] = s;
        }
        __syncthreads();
        int excl = s_carry + x - v + (w ? warpsum[w - 1] : 0);
        if (i < n) { g_off[i] = excl; g_cursor[i] = excl; }
        int tot = warpsum[31];
        __syncthreads();
        if (t == 0) s_carry += tot;
        __syncthreads();
    }
    if (t == 0) g_off[n] = s_carry;
}

__global__ void scatter_kernel(const int* __restrict__ src, const int* __restrict__ dst,
                               const int* __restrict__ et, int e_cnt) {
    for (int e = blockIdx.x * blockDim.x + threadIdx.x; e < e_cnt; e += gridDim.x * blockDim.x) {
        int p = atomicAdd(&g_cursor[dst[e]], 1);
        g_edge[p] = make_int2(src[e], et[e]);
    }
}

// ---------------- fused layer: TC aggregation -> smem A tile -> TC GEMM ----------------
// Block: 64 nodes, 16 warps. Warp aggregates 4 nodes (16-edge MMA chunks), deposits
// swizzled fp16 rows into the 64x1088 smem A tile; then 4x4 warp grid computes
// A @ WcT^T (B cp.async double-buffered, stage0 prefetched before aggregation).
__global__ void __launch_bounds__(THREADS, 1)
fused_layer_kernel(const float* __restrict__ cmat, const float* __restrict__ bias,
                   int layer, int n_nodes) {
    extern __shared__ __align__(16) char sm[];
    __shared__ __align__(16) __half c16[33 * 16];   // row 32 = zeros (padding rows)
    __half* sA = (__half*)sm;
    const __half* __restrict__ hin = (layer == 0) ? g_hp16 : g_h1;
    const __half* __restrict__ Bt  = (layer == 0) ? g_WcT0 : g_WcT1;

    int t = threadIdx.x, w = t >> 5, lane = t & 31;
    int g = lane >> 2, tig = lane & 3;
    int blockRow = blockIdx.x * NODES_BLK;

    // prefetch B stage 0 (1x 16B per thread), hidden under aggregation
    {
        int n = t >> 3, seg = t & 7;
        const __half* src = Bt + (size_t)n * KTOT + seg * 8;
        uint32_t dst = (uint32_t)__cvta_generic_to_shared(sm + OFF_B + (n * BRS + seg * 8) * 2);
        CP_ASYNC16(dst, src);
        asm volatile("cp.async.commit_group;");
    }

    for (int i = t; i < 32 * 16; i += THREADS) c16[i] = __float2half_rn(cmat[i]);
    for (int i = 32 * 16 + t; i < 33 * 16; i += THREADS) c16[i] = __ushort_as_half(0);
    __syncthreads();

    // ---- aggregation phase: warp-private staging, 4 nodes per warp ----
    {
        uint32_t hb = (uint32_t)__cvta_generic_to_shared(sm + OFF_HST + w * 16 * HSTR * 2);
        uint32_t cb = (uint32_t)__cvta_generic_to_shared(sm + OFF_CST + w * 16 * CSTR * 2);
        uint32_t aaddr = cb + (uint32_t)((((lane & 7) + ((lane & 16) >> 1)) * CSTR + (lane & 8)) * 2);
        uint32_t baddr = hb + (uint32_t)(((lane & 15) * HSTR + ((lane & 16) >> 1)) * 2);
        int row = lane >> 1, part = lane & 1;

        #pragma unroll 1
        for (int rep = 0; rep < NPW; rep++) {
            int local = w * NPW + rep;
            int n = blockRow + local;
            if (n >= n_nodes) break;

            float acc[8][4];
            #pragma unroll
            for (int i = 0; i < 8; i++)
                #pragma unroll
                for (int j = 0; j < 4; j++) acc[i][j] = 0.f;

            int beg = g_off[n], end = g_off[n + 1];
            for (int kc = beg; kc < end; kc += 16) {
                __syncwarp();                               // WAR: prior ldsm done
                int ei = kc + row;
                int ec = (ei < end) ? ei : end - 1;
                int2 e = g_edge[ec];
                int rsel = (ei < end) ? e.y : 32;
                const uint4* hsrc = (const uint4*)(hin + (size_t)e.x * DD + part * 32);
                uint4 v0 = hsrc[0], v1 = hsrc[1], v2 = hsrc[2], v3 = hsrc[3];
                uint4* hdst = (uint4*)(sm + OFF_HST + (w * 16 * HSTR + row * HSTR + part * 32) * 2);
                hdst[0] = v0; hdst[1] = v1; hdst[2] = v2; hdst[3] = v3;
                *(uint4*)(sm + OFF_CST + (w * 16 * CSTR + row * CSTR + part * 8) * 2) =
                    *(const uint4*)(c16 + rsel * 16 + part * 8);
                __syncwarp();                               // RAW: stage visible

                uint32_t a0, a1, a2, a3;
                LDSM_X4_T(a0, a1, a2, a3, aaddr);
                #pragma unroll
                for (int dt = 0; dt < 4; dt++) {
                    uint32_t b0, b1, b2, b3;
                    LDSM_X4_T(b0, b1, b2, b3, baddr + dt * 32);
                    MMA16816(acc[2 * dt],     a0, a1, a2, a3, b0, b1);
                    MMA16816(acc[2 * dt + 1], a0, a1, a2, a3, b2, b3);
                }
            }

            // deposit swizzled A row: k = b*64 + dt*8 + 2*tig, chunk = b*8+dt -> swz
            __half* arow = sA + (size_t)local * ASTR;
            #pragma unroll
            for (int dt = 0; dt < 8; dt++) {
                int p0 = (g * 8 + (dt ^ g)) * 8 + 2 * tig;          // b = g
                int p1 = ((g + 8) * 8 + (dt ^ g)) * 8 + 2 * tig;    // b = g+8
                *(__half2*)(arow + p0) = __floats2half2_rn(acc[dt][0], acc[dt][1]);
                *(__half2*)(arow + p1) = __floats2half2_rn(acc[dt][2], acc[dt][3]);
            }
            // self-loop: k = 1024 + 2*lane (chunk 128+g: swz identity)
            *(uint32_t*)(arow + 1024 + 2 * lane) = ((const uint32_t*)(hin + (size_t)n * DD))[lane];
        }
    }
    __syncthreads();

    // ---- GEMM phase: (64 x 1088) @ (1088 x 64), 16 warps m16n16 ----
    int wr = w >> 2, wc = w & 3;
    float c[2][4];
    #pragma unroll
    for (int nb = 0; nb < 2; nb++)
        #pragma unroll
        for (int q = 0; q < 4; q++) c[nb][q] = 0.f;

    int arow0 = (wr * 16 + g) * ASTR;

    #pragma unroll 1
    for (int ks = 0; ks < NBSTAGES; ks++) {
        if (ks + 1 < NBSTAGES) {
            int n = t >> 3, seg = t & 7;
            const __half* src = Bt + (size_t)n * KTOT + (ks + 1) * 64 + seg * 8;
            uint32_t dst = (uint32_t)__cvta_generic_to_shared(
                sm + OFF_B + ((ks + 1) & 1) * B_STG_B + (n * BRS + seg * 8) * 2);
            CP_ASYNC16(dst, src);
        }
        asm volatile("cp.async.commit_group;");
        asm volatile("cp.async.wait_group 1;");
        __syncthreads();

        const __half* Bs = (const __half*)(sm + OFF_B + (ks & 1) * B_STG_B);
        #pragma unroll
        for (int k16 = 0; k16 < 4; k16++) {
            int kb = ks * 64 + k16 * 16;
            int c0 = kb >> 3;
            int p0 = swz(c0) * 8 + 2 * tig;
            int p1 = swz(c0 + 1) * 8 + 2 * tig;
            uint32_t a0 = *(const uint32_t*)(sA + arow0 + p0);
            uint32_t a1 = *(const uint32_t*)(sA + arow0 + 8 * ASTR + p0);
            uint32_t a2 = *(const uint32_t*)(sA + arow0 + p1);
            uint32_t a3 = *(const uint32_t*)(sA + arow0 + 8 * ASTR + p1);
            #pragma unroll
            for (int nb = 0; nb < 2; nb++) {
                const __half* bb = Bs + (wc * 16 + nb * 8 + g) * BRS + k16 * 16 + 2 * tig;
                uint32_t b0 = *(const uint32_t*)(bb);
                uint32_t b1 = *(const uint32_t*)(bb + 8);
                MMA16816(c[nb], a0, a1, a2, a3, b0, b1);
            }
        }
        __syncthreads();
    }

    // epilogue: bias (+relu); layer0 -> fp16 g_h1, layer1 -> fp32 g_h2
    #pragma unroll
    for (int nb = 0; nb < 2; nb++) {
        int colb = wc * 16 + nb * 8 + 2 * tig;
        int row0 = blockRow + wr * 16 + g;
        float bb0 = bias[colb], bb1 = bias[colb + 1];
        float v00 = c[nb][0] + bb0, v01 = c[nb][1] + bb1;
        float v10 = c[nb][2] + bb0, v11 = c[nb][3] + bb1;
        if (layer == 0) {
            v00 = fmaxf(v00, 0.f); v01 = fmaxf(v01, 0.f);
            v10 = fmaxf(v10, 0.f); v11 = fmaxf(v11, 0.f);
            if (row0 < n_nodes)
                *(__half2*)(g_h1 + (size_t)row0 * DD + colb) = __floats2half2_rn(v00, v01);
            if (row0 + 8 < n_nodes)
                *(__half2*)(g_h1 + (size_t)(row0 + 8) * DD + colb) = __floats2half2_rn(v10, v11);
        } else {
            if (row0 < n_nodes)
                *(float2*)(g_h2 + (size_t)row0 * DD + colb) = make_float2(v00, v01);
            if (row0 + 8 < n_nodes)
                *(float2*)(g_h2 + (size_t)(row0 + 8) * DD + colb) = make_float2(v10, v11);
        }
    }
}

// ---------------- DistMult scoring: warp per triplet ----------------
__global__ void score_kernel(const int* __restrict__ head, const int* __restrict__ rel,
                             const int* __restrict__ tail, const float* __restrict__ wrel,
                             float* __restrict__ out, int t_cnt) {
    int w = (blockIdx.x * blockDim.x + threadIdx.x) >> 5;
    int lane = threadIdx.x & 31;
    if (w >= t_cnt) return;
    float2 a = *(const float2*)(g_h2 + (size_t)head[w] * DD + 2 * lane);
    float2 r = *(const float2*)(wrel + (size_t)rel[w] * DD + 2 * lane);
    float2 b = *(const float2*)(g_h2 + (size_t)tail[w] * DD + 2 * lane);
    float p = a.x * r.x * b.x + a.y * r.y * b.y;
    #pragma unroll
    for (int d = 16; d > 0; d >>= 1) p += __shfl_xor_sync(0xffffffffu, p, d);
    if (lane == 0) out[w] = p;
}

// ---------------- launch ----------------
extern "C" void kernel_launch(void* const* d_in, const int* in_sizes, int n_in,
                              void* d_out, int out_size) {
    const int*   src   = (const int*)d_in[0];
    const int*   dst   = (const int*)d_in[1];
    const int*   ety   = (const int*)d_in[2];
    const int*   head  = (const int*)d_in[3];
    const int*   rel   = (const int*)d_in[4];
    const int*   tail  = (const int*)d_in[5];
    const float* embed = (const float*)d_in[6];
    const float* v0    = (const float*)d_in[7];
    const float* c0    = (const float*)d_in[8];
    const float* wl0   = (const float*)d_in[9];
    const float* b0    = (const float*)d_in[10];
    const float* v1    = (const float*)d_in[11];
    const float* c1    = (const float*)d_in[12];
    const float* wl1   = (const float*)d_in[13];
    const float* b1    = (const float*)d_in[14];
    const float* wrel  = (const float*)d_in[15];
    float* out = (float*)d_out;

    int E = in_sizes[0];
    int T = in_sizes[3];
    int N = in_sizes[6] / DD;
    if (N > NN) N = NN;
    if (E > EE) E = EE;
    if (T > TT) T = TT;

    cudaFuncSetAttribute(fused_layer_kernel,
                         cudaFuncAttributeMaxDynamicSharedMemorySize, SMEM_TOTAL);

    // prep: CSR by dst + fp16 repacks + B^T build
    zero_indeg_kernel<<<(N + 255) / 256, 256>>>(N);
    pack_h_kernel<<<(N * 32 + 255) / 256, 256>>>(embed, N);
    build_wct_kernel<<<(DD * KTOT + 255) / 256, 256>>>(v0, wl0, v1, wl1);
    hist_kernel<<<1024, 256>>>(dst, E);
    scan_kernel<<<1, 1024>>>(N);
    scatter_kernel<<<1024, 256>>>(src, dst, ety, E);

    int grid = (N + NODES_BLK - 1) / NODES_BLK;
    fused_layer_kernel<<<grid, THREADS, SMEM_TOTAL>>>(c0, b0, 0, N);   // layer 0 (relu)
    fused_layer_kernel<<<grid, THREADS, SMEM_TOTAL>>>(c1, b1, 1, N);   // layer 1

    // DistMult scoring
    score_kernel<<<(T + 7) / 8, 256>>>(head, rel, tail, wrel, out, T);
}